// round 1
// baseline (speedup 1.0000x reference)
#include <cuda_runtime.h>
#include <cstdint>

// ---------------------------------------------------------------------------
// VQ-VAE quantizer:
//   x      [4, 64, 32, 32, 32] fp32   (b, c, h, w, d), c = embed dim = 64
//   weight [512, 64] fp32             codebook
// outputs (concatenated fp32 in d_out):
//   quantized_st [4, 64, 32, 32, 32]  = weight[argmin] scattered back
//   embed_idx    [4, 32, 32, 32]      (as float)
//   latent_loss  [1]                  = 0.25 * mean((q - x)^2)
//
// argmin_j ||x - w_j||^2 == argmin_j ( ||w_j||^2 - 2 x.w_j )   (xsq is const)
// ---------------------------------------------------------------------------

#define FMA_F32X2(d, a, b, c) \
    asm("fma.rn.f32x2 %0, %1, %2, %3;" : "=l"(d) : "l"(a), "l"(b), "l"(c))
#define ADD_F32X2(d, a, b) \
    asm("add.rn.f32x2 %0, %1, %2;" : "=l"(d) : "l"(a), "l"(b))
#define PACK_F32X2(d, lo, hi) \
    asm("mov.b64 %0, {%1, %2};" : "=l"(d) : "f"(lo), "f"(hi))
#define UNPACK_F32X2(lo, hi, v) \
    asm("mov.b64 {%0, %1}, %2;" : "=f"(lo), "=f"(hi) : "l"(v))

static constexpr int C = 64;     // embed dim
static constexpr int E = 512;    // codebook entries
static constexpr int S = 32768;  // 32*32*32 spatial positions per batch

// scratch (no device allocation allowed)
__device__ int   g_idx[1 << 18];
__device__ float g_partials[8192];

// ---------------------------------------------------------------------------
// Kernel 1: argmin over codebook. One thread = one spatial position.
// Codebook + wsq live in shared memory (130 KB -> 1 block/SM).
// x for this position packed into 32 x b64 registers (f32x2 pairs).
// ---------------------------------------------------------------------------
__global__ void __launch_bounds__(512, 1) argmin_kernel(
    const float* __restrict__ x, const float* __restrict__ w,
    float* __restrict__ out_idx, int npos)
{
    extern __shared__ float smem[];
    float* ws  = smem;          // [E*C]
    float* wsq = smem + E * C;  // [E]

    const int tid = threadIdx.x;

    // cooperative load of codebook (float4 = 128B per warp per iter)
    for (int i = tid; i < E * C / 4; i += blockDim.x)
        ((float4*)ws)[i] = ((const float4*)w)[i];
    __syncthreads();

    // wsq[j] = sum_c w[j][c]^2
    for (int j = tid; j < E; j += blockDim.x) {
        float ssum = 0.f;
        #pragma unroll
        for (int c = 0; c < C; ++c) {
            float v = ws[j * C + c];
            ssum = fmaf(v, v, ssum);
        }
        wsq[j] = ssum;
    }
    __syncthreads();

    const int p = blockIdx.x * blockDim.x + tid;
    if (p >= npos) return;
    const int b = p / S;
    const int s = p - b * S;
    const float* xp = x + (size_t)b * C * S + s;

    // load this position's 64 channels, packed into f32x2 pairs
    unsigned long long xv[C / 2];
    #pragma unroll
    for (int k = 0; k < C / 2; ++k) {
        float lo = xp[(size_t)(2 * k) * S];
        float hi = xp[(size_t)(2 * k + 1) * S];
        PACK_F32X2(xv[k], lo, hi);
    }

    float best = 3.4e38f;
    int bestj = 0;

    for (int j = 0; j < E; ++j) {
        const ulonglong2* wrow = (const ulonglong2*)(ws + j * C);
        unsigned long long a0 = 0ull, a1 = 0ull, a2 = 0ull, a3 = 0ull;
        #pragma unroll
        for (int k = 0; k < C / 4; ++k) {          // 16 iters: LDS.128 + 2x FFMA2
            ulonglong2 wv = wrow[k];
            unsigned long long xa = xv[2 * k], xb = xv[2 * k + 1];
            if ((k & 1) == 0) {
                FMA_F32X2(a0, xa, wv.x, a0);
                FMA_F32X2(a1, xb, wv.y, a1);
            } else {
                FMA_F32X2(a2, xa, wv.x, a2);
                FMA_F32X2(a3, xb, wv.y, a3);
            }
        }
        unsigned long long s01, s23, sA;
        ADD_F32X2(s01, a0, a1);
        ADD_F32X2(s23, a2, a3);
        ADD_F32X2(sA, s01, s23);
        float lo, hi;
        UNPACK_F32X2(lo, hi, sA);
        float dot = lo + hi;
        float d = fmaf(-2.f, dot, wsq[j]);
        if (d < best) { best = d; bestj = j; }     // strict < => first min (argmin tie rule)
    }

    g_idx[p]   = bestj;
    out_idx[p] = (float)bestj;
}

// ---------------------------------------------------------------------------
// Kernel 2: scatter quantized values + per-block loss partials.
// One thread per output element (grid-stride), coalesced x read + q write;
// codebook gathers are L2-resident (128 KB).
// ---------------------------------------------------------------------------
__global__ void __launch_bounds__(256) quant_loss_kernel(
    const float* __restrict__ x, const float* __restrict__ w,
    float* __restrict__ out_q, int nelem)
{
    const int tid = threadIdx.x;
    float acc = 0.f;
    const int stride = gridDim.x * blockDim.x;
    for (int e = blockIdx.x * blockDim.x + tid; e < nelem; e += stride) {
        const int s = e & (S - 1);           // e = ((b*64)+c)*32768 + s
        const int c = (e >> 15) & (C - 1);
        const int b = e >> 21;
        const int p = b * S + s;
        const float q = w[g_idx[p] * C + c];
        out_q[e] = q;
        const float d = q - x[e];
        acc = fmaf(d, d, acc);
    }
    __shared__ float red[256];
    red[tid] = acc;
    __syncthreads();
    #pragma unroll
    for (int off = 128; off > 0; off >>= 1) {
        if (tid < off) red[tid] += red[tid + off];
        __syncthreads();
    }
    if (tid == 0) g_partials[blockIdx.x] = red[0];
}

// ---------------------------------------------------------------------------
// Kernel 3: deterministic final reduction of loss partials.
// ---------------------------------------------------------------------------
__global__ void __launch_bounds__(1024) loss_final_kernel(
    float* __restrict__ out_loss, int nblocks, float inv_n)
{
    __shared__ float red[1024];
    const int tid = threadIdx.x;
    float a = 0.f;
    for (int i = tid; i < nblocks; i += 1024) a += g_partials[i];
    red[tid] = a;
    __syncthreads();
    #pragma unroll
    for (int off = 512; off > 0; off >>= 1) {
        if (tid < off) red[tid] += red[tid + off];
        __syncthreads();
    }
    if (tid == 0) out_loss[0] = 0.25f * red[0] * inv_n;
}

// ---------------------------------------------------------------------------
extern "C" void kernel_launch(void* const* d_in, const int* in_sizes, int n_in,
                              void* d_out, int out_size)
{
    const float* x = (const float*)d_in[0];
    const float* w = (const float*)d_in[1];
    float* out = (float*)d_out;

    const int n_x  = in_sizes[0];   // 8388608
    const int npos = n_x / C;       // 131072

    float* out_q    = out;
    float* out_idx  = out + n_x;
    float* out_loss = out + n_x + npos;

    const int smem_bytes = (E * C + E) * (int)sizeof(float);
    cudaFuncSetAttribute(argmin_kernel,
                         cudaFuncAttributeMaxDynamicSharedMemorySize, smem_bytes);

    const int blocks1 = (npos + 511) / 512;
    argmin_kernel<<<blocks1, 512, smem_bytes>>>(x, w, out_idx, npos);

    const int blocks2 = 4096;
    quant_loss_kernel<<<blocks2, 256>>>(x, w, out_q, n_x);

    loss_final_kernel<<<1, 1024>>>(out_loss, blocks2, 1.0f / (float)n_x);
}

// round 2
// speedup vs baseline: 1.2280x; 1.2280x over previous
#include <cuda_runtime.h>
#include <cstdint>

// ---------------------------------------------------------------------------
// VQ-VAE quantizer:
//   x      [4, 64, 32, 32, 32] fp32   (b, c, h, w, d), c = embed dim = 64
//   weight [512, 64] fp32             codebook
// outputs (concatenated fp32 in d_out):
//   quantized_st [4, 64, 32, 32, 32]
//   embed_idx    [4, 32, 32, 32]  (as float)
//   latent_loss  [1]
//
// argmin_j ||x - w_j||^2 == argmin_j ( ||w_j||^2 - 2 x.w_j )
// Round 2: 2 positions per thread to amortize codebook LDS (was LDS-bound:
// L1=80%, fma=42.7%). Now 16 LDS.128 feed 64 FFMA2 per code per warp.
// ---------------------------------------------------------------------------

#define FMA_F32X2(d, a, b, c) \
    asm("fma.rn.f32x2 %0, %1, %2, %3;" : "=l"(d) : "l"(a), "l"(b), "l"(c))
#define ADD_F32X2(d, a, b) \
    asm("add.rn.f32x2 %0, %1, %2;" : "=l"(d) : "l"(a), "l"(b))
#define PACK_F32X2(d, lo, hi) \
    asm("mov.b64 %0, {%1, %2};" : "=l"(d) : "f"(lo), "f"(hi))
#define UNPACK_F32X2(lo, hi, v) \
    asm("mov.b64 {%0, %1}, %2;" : "=f"(lo), "=f"(hi) : "l"(v))

static constexpr int C = 64;     // embed dim
static constexpr int E = 512;    // codebook entries
static constexpr int S = 32768;  // spatial positions per batch

__device__ int   g_idx[1 << 18];
__device__ float g_partials[8192];

// ---------------------------------------------------------------------------
// Kernel 1: argmin. 256 threads/block, 2 positions/thread (512 pos/block).
// Codebook (128KB) + wsq in smem; x held in packed f32x2 registers.
// ---------------------------------------------------------------------------
__global__ void __launch_bounds__(256, 1) argmin_kernel(
    const float* __restrict__ x, const float* __restrict__ w,
    float* __restrict__ out_idx, int npos)
{
    extern __shared__ float smem[];
    float* ws  = smem;          // [E*C]
    float* wsq = smem + E * C;  // [E]

    const int tid = threadIdx.x;

    for (int i = tid; i < E * C / 4; i += blockDim.x)
        ((float4*)ws)[i] = ((const float4*)w)[i];
    __syncthreads();

    for (int j = tid; j < E; j += blockDim.x) {
        float ssum = 0.f;
        #pragma unroll
        for (int c = 0; c < C; ++c) {
            float v = ws[j * C + c];
            ssum = fmaf(v, v, ssum);
        }
        wsq[j] = ssum;
    }
    __syncthreads();

    const int p0 = blockIdx.x * 512 + tid;   // first position
    const int p1 = p0 + 256;                 // second position
    if (p0 >= npos) return;

    // x pointers (channel stride = S within a batch)
    const int b0 = p0 >> 15, s0 = p0 & (S - 1);
    const int b1 = p1 >> 15, s1 = p1 & (S - 1);
    const float* xp0 = x + (size_t)b0 * C * S + s0;
    const float* xp1 = x + (size_t)b1 * C * S + s1;

    unsigned long long xv0[C / 2], xv1[C / 2];
    #pragma unroll
    for (int k = 0; k < C / 2; ++k) {
        float lo = xp0[(size_t)(2 * k) * S];
        float hi = xp0[(size_t)(2 * k + 1) * S];
        PACK_F32X2(xv0[k], lo, hi);
        lo = xp1[(size_t)(2 * k) * S];
        hi = xp1[(size_t)(2 * k + 1) * S];
        PACK_F32X2(xv1[k], lo, hi);
    }

    float best0 = 3.4e38f, best1 = 3.4e38f;
    int bestj0 = 0, bestj1 = 0;

    for (int j = 0; j < E; ++j) {
        const ulonglong2* wrow = (const ulonglong2*)(ws + j * C);
        unsigned long long a0 = 0ull, a1 = 0ull, a2 = 0ull, a3 = 0ull;
        unsigned long long c0 = 0ull, c1 = 0ull, c2 = 0ull, c3 = 0ull;
        #pragma unroll
        for (int k = 0; k < C / 4; ++k) {   // 16 iters: 1 LDS.128 + 4 FFMA2
            ulonglong2 wv = wrow[k];
            if ((k & 1) == 0) {
                FMA_F32X2(a0, xv0[2 * k],     wv.x, a0);
                FMA_F32X2(a1, xv0[2 * k + 1], wv.y, a1);
                FMA_F32X2(c0, xv1[2 * k],     wv.x, c0);
                FMA_F32X2(c1, xv1[2 * k + 1], wv.y, c1);
            } else {
                FMA_F32X2(a2, xv0[2 * k],     wv.x, a2);
                FMA_F32X2(a3, xv0[2 * k + 1], wv.y, a3);
                FMA_F32X2(c2, xv1[2 * k],     wv.x, c2);
                FMA_F32X2(c3, xv1[2 * k + 1], wv.y, c3);
            }
        }
        const float wq = wsq[j];
        {
            unsigned long long s01, s23, sA;
            ADD_F32X2(s01, a0, a1);
            ADD_F32X2(s23, a2, a3);
            ADD_F32X2(sA, s01, s23);
            float lo, hi;
            UNPACK_F32X2(lo, hi, sA);
            float d = fmaf(-2.f, lo + hi, wq);
            if (d < best0) { best0 = d; bestj0 = j; }
        }
        {
            unsigned long long s01, s23, sA;
            ADD_F32X2(s01, c0, c1);
            ADD_F32X2(s23, c2, c3);
            ADD_F32X2(sA, s01, s23);
            float lo, hi;
            UNPACK_F32X2(lo, hi, sA);
            float d = fmaf(-2.f, lo + hi, wq);
            if (d < best1) { best1 = d; bestj1 = j; }
        }
    }

    g_idx[p0]   = bestj0;
    out_idx[p0] = (float)bestj0;
    if (p1 < npos) {
        g_idx[p1]   = bestj1;
        out_idx[p1] = (float)bestj1;
    }
}

// ---------------------------------------------------------------------------
// Kernel 2: scatter quantized values + loss partials, float4-vectorized.
// e = ((b*64)+c)*32768 + s ; 4 consecutive e share b,c; s..s+3 consecutive.
// ---------------------------------------------------------------------------
__global__ void __launch_bounds__(256) quant_loss_kernel(
    const float* __restrict__ x, const float* __restrict__ w,
    float* __restrict__ out_q, int nelem)
{
    const int tid = threadIdx.x;
    const int nvec = nelem >> 2;
    float acc = 0.f;
    const int stride = gridDim.x * blockDim.x;
    for (int v = blockIdx.x * blockDim.x + tid; v < nvec; v += stride) {
        const int e = v << 2;
        const int s = e & (S - 1);
        const int c = (e >> 15) & (C - 1);
        const int b = e >> 21;
        const int p = b * S + s;
        float4 q;
        q.x = w[g_idx[p]     * C + c];
        q.y = w[g_idx[p + 1] * C + c];
        q.z = w[g_idx[p + 2] * C + c];
        q.w = w[g_idx[p + 3] * C + c];
        const float4 xv = ((const float4*)x)[v];
        ((float4*)out_q)[v] = q;
        float d;
        d = q.x - xv.x; acc = fmaf(d, d, acc);
        d = q.y - xv.y; acc = fmaf(d, d, acc);
        d = q.z - xv.z; acc = fmaf(d, d, acc);
        d = q.w - xv.w; acc = fmaf(d, d, acc);
    }
    __shared__ float red[256];
    red[tid] = acc;
    __syncthreads();
    #pragma unroll
    for (int off = 128; off > 0; off >>= 1) {
        if (tid < off) red[tid] += red[tid + off];
        __syncthreads();
    }
    if (tid == 0) g_partials[blockIdx.x] = red[0];
}

// ---------------------------------------------------------------------------
__global__ void __launch_bounds__(1024) loss_final_kernel(
    float* __restrict__ out_loss, int nblocks, float inv_n)
{
    __shared__ float red[1024];
    const int tid = threadIdx.x;
    float a = 0.f;
    for (int i = tid; i < nblocks; i += 1024) a += g_partials[i];
    red[tid] = a;
    __syncthreads();
    #pragma unroll
    for (int off = 512; off > 0; off >>= 1) {
        if (tid < off) red[tid] += red[tid + off];
        __syncthreads();
    }
    if (tid == 0) out_loss[0] = 0.25f * red[0] * inv_n;
}

// ---------------------------------------------------------------------------
extern "C" void kernel_launch(void* const* d_in, const int* in_sizes, int n_in,
                              void* d_out, int out_size)
{
    const float* x = (const float*)d_in[0];
    const float* w = (const float*)d_in[1];
    float* out = (float*)d_out;

    const int n_x  = in_sizes[0];   // 8388608
    const int npos = n_x / C;       // 131072

    float* out_q    = out;
    float* out_idx  = out + n_x;
    float* out_loss = out + n_x + npos;

    const int smem_bytes = (E * C + E) * (int)sizeof(float);
    cudaFuncSetAttribute(argmin_kernel,
                         cudaFuncAttributeMaxDynamicSharedMemorySize, smem_bytes);

    const int blocks1 = (npos + 511) / 512;   // 256
    argmin_kernel<<<blocks1, 256, smem_bytes>>>(x, w, out_idx, npos);

    const int blocks2 = 2048;
    quant_loss_kernel<<<blocks2, 256>>>(x, w, out_q, n_x);

    loss_final_kernel<<<1, 1024>>>(out_loss, blocks2, 1.0f / (float)n_x);
}

// round 3
// speedup vs baseline: 1.3710x; 1.1165x over previous
#include <cuda_runtime.h>
#include <cstdint>

// ---------------------------------------------------------------------------
// VQ-VAE quantizer, fused single-pass version.
//   x      [4, 64, 32, 32, 32] fp32   (b, c, h, w, d), c = embed dim = 64
//   weight [512, 64] fp32             codebook
// outputs (concatenated fp32 in d_out):
//   quantized_st [4, 64, 32, 32, 32] = fl(fl(w[idx]-x)+x)  (mimics stop_grad)
//   embed_idx    [4, 32, 32, 32]  (as float)
//   latent_loss  [1] = 0.25*mean((w[idx]-x)^2)
//
// argmin_j ||x - w_j||^2 == argmin_j ( ||w_j||^2 - 2 x.w_j )
// Round 3: persistent grid 148, fused q-write + loss epilogue (kernel2 gone),
// padded codebook rows (68 floats) for conflict-light epilogue gather,
// unroll-2 j-loop for LDS/FMA overlap. Dot-product association identical to
// round 2 (argmin bit-stable).
// ---------------------------------------------------------------------------

#define FMA_F32X2(d, a, b, c) \
    asm("fma.rn.f32x2 %0, %1, %2, %3;" : "=l"(d) : "l"(a), "l"(b), "l"(c))
#define ADD_F32X2(d, a, b) \
    asm("add.rn.f32x2 %0, %1, %2;" : "=l"(d) : "l"(a), "l"(b))
#define PACK_F32X2(d, lo, hi) \
    asm("mov.b64 %0, {%1, %2};" : "=l"(d) : "f"(lo), "f"(hi))
#define UNPACK_F32X2(lo, hi, v) \
    asm("mov.b64 {%0, %1}, %2;" : "=f"(lo), "=f"(hi) : "l"(v))

static constexpr int C  = 64;     // embed dim
static constexpr int E  = 512;    // codebook entries
static constexpr int S  = 32768;  // spatial positions per batch
static constexpr int RP = 68;     // padded codebook row (floats): 272B, 16B-aligned

static constexpr int GRID    = 148;  // one persistent block per SM
static constexpr int THREADS = 256;
static constexpr int PPB     = 512;            // positions per block per chunk (2/thread)
static constexpr int CHUNK   = GRID * PPB;     // 75776 positions per chunk

__device__ float g_partials[GRID];

// ---------------------------------------------------------------------------
__global__ void __launch_bounds__(THREADS, 1) vq_fused_kernel(
    const float* __restrict__ x, const float* __restrict__ w,
    float* __restrict__ out_q, float* __restrict__ out_idx, int npos)
{
    extern __shared__ float smem[];
    float* ws  = smem;            // [E][RP]
    float* wsq = smem + E * RP;   // [E]

    const int tid = threadIdx.x;

    // cooperative load of codebook into padded rows
    for (int i = tid; i < E * C / 4; i += THREADS) {
        const int j = i >> 4;          // 16 float4 per logical row
        const int k = i & 15;
        ((float4*)(ws + j * RP))[k] = ((const float4*)w)[i];
    }
    __syncthreads();

    for (int j = tid; j < E; j += THREADS) {
        float ssum = 0.f;
        #pragma unroll
        for (int c = 0; c < C; ++c) {
            const float v = ws[j * RP + c];
            ssum = fmaf(v, v, ssum);
        }
        wsq[j] = ssum;
    }
    __syncthreads();

    float acc_loss = 0.f;

    #pragma unroll 1
    for (int chunk = 0; chunk < 2; ++chunk) {
        const int p0 = chunk * CHUNK + blockIdx.x * PPB + tid;
        const int p1 = p0 + THREADS;
        if (p0 >= npos) continue;   // block-uniform in this geometry

        const int b0 = p0 >> 15, s0 = p0 & (S - 1);
        const int b1 = p1 >> 15, s1 = p1 & (S - 1);
        const float* xp0 = x + (size_t)b0 * C * S + s0;
        const float* xp1 = x + (size_t)b1 * C * S + s1;

        unsigned long long xv0[C / 2], xv1[C / 2];
        #pragma unroll
        for (int k = 0; k < C / 2; ++k) {
            float lo = xp0[(size_t)(2 * k) * S];
            float hi = xp0[(size_t)(2 * k + 1) * S];
            PACK_F32X2(xv0[k], lo, hi);
            lo = xp1[(size_t)(2 * k) * S];
            hi = xp1[(size_t)(2 * k + 1) * S];
            PACK_F32X2(xv1[k], lo, hi);
        }

        float best0 = 3.4e38f, best1 = 3.4e38f;
        int bestj0 = 0, bestj1 = 0;

        #pragma unroll 2
        for (int j = 0; j < E; ++j) {
            const ulonglong2* wrow = (const ulonglong2*)(ws + j * RP);
            unsigned long long a0 = 0ull, a1 = 0ull, a2 = 0ull, a3 = 0ull;
            unsigned long long c0 = 0ull, c1 = 0ull, c2 = 0ull, c3 = 0ull;
            #pragma unroll
            for (int k = 0; k < C / 4; ++k) {   // 16x: LDS.128 + 4 FFMA2
                const ulonglong2 wv = wrow[k];
                if ((k & 1) == 0) {
                    FMA_F32X2(a0, xv0[2 * k],     wv.x, a0);
                    FMA_F32X2(a1, xv0[2 * k + 1], wv.y, a1);
                    FMA_F32X2(c0, xv1[2 * k],     wv.x, c0);
                    FMA_F32X2(c1, xv1[2 * k + 1], wv.y, c1);
                } else {
                    FMA_F32X2(a2, xv0[2 * k],     wv.x, a2);
                    FMA_F32X2(a3, xv0[2 * k + 1], wv.y, a3);
                    FMA_F32X2(c2, xv1[2 * k],     wv.x, c2);
                    FMA_F32X2(c3, xv1[2 * k + 1], wv.y, c3);
                }
            }
            const float wq = wsq[j];
            {
                unsigned long long s01, s23, sA;
                ADD_F32X2(s01, a0, a1);
                ADD_F32X2(s23, a2, a3);
                ADD_F32X2(sA, s01, s23);
                float lo, hi;
                UNPACK_F32X2(lo, hi, sA);
                const float d = fmaf(-2.f, lo + hi, wq);
                if (d < best0) { best0 = d; bestj0 = j; }
            }
            {
                unsigned long long s01, s23, sA;
                ADD_F32X2(s01, c0, c1);
                ADD_F32X2(s23, c2, c3);
                ADD_F32X2(sA, s01, s23);
                float lo, hi;
                UNPACK_F32X2(lo, hi, sA);
                const float d = fmaf(-2.f, lo + hi, wq);
                if (d < best1) { best1 = d; bestj1 = j; }
            }
        }

        out_idx[p0] = (float)bestj0;
        out_idx[p1] = (float)bestj1;

        // fused epilogue: q = fl(fl(w-x)+x), loss += (w-x)^2
        const float* wr0 = ws + bestj0 * RP;
        const float* wr1 = ws + bestj1 * RP;
        float* q0 = out_q + (size_t)b0 * C * S + s0;
        float* q1 = out_q + (size_t)b1 * C * S + s1;
        #pragma unroll
        for (int k = 0; k < C / 2; ++k) {
            float x0lo, x0hi, x1lo, x1hi;
            UNPACK_F32X2(x0lo, x0hi, xv0[k]);
            UNPACK_F32X2(x1lo, x1hi, xv1[k]);

            float d00 = wr0[2 * k]     - x0lo;
            float d01 = wr0[2 * k + 1] - x0hi;
            float d10 = wr1[2 * k]     - x1lo;
            float d11 = wr1[2 * k + 1] - x1hi;

            q0[(size_t)(2 * k) * S]     = d00 + x0lo;
            q0[(size_t)(2 * k + 1) * S] = d01 + x0hi;
            q1[(size_t)(2 * k) * S]     = d10 + x1lo;
            q1[(size_t)(2 * k + 1) * S] = d11 + x1hi;

            acc_loss = fmaf(d00, d00, acc_loss);
            acc_loss = fmaf(d01, d01, acc_loss);
            acc_loss = fmaf(d10, d10, acc_loss);
            acc_loss = fmaf(d11, d11, acc_loss);
        }
    }

    // block-level loss reduction (all threads reach here)
    __shared__ float red[THREADS];
    red[tid] = acc_loss;
    __syncthreads();
    #pragma unroll
    for (int off = THREADS / 2; off > 0; off >>= 1) {
        if (tid < off) red[tid] += red[tid + off];
        __syncthreads();
    }
    if (tid == 0) g_partials[blockIdx.x] = red[0];
}

// ---------------------------------------------------------------------------
__global__ void __launch_bounds__(256) loss_final_kernel(
    float* __restrict__ out_loss, int nblocks, float inv_n)
{
    __shared__ float red[256];
    const int tid = threadIdx.x;
    float a = 0.f;
    for (int i = tid; i < nblocks; i += 256) a += g_partials[i];
    red[tid] = a;
    __syncthreads();
    #pragma unroll
    for (int off = 128; off > 0; off >>= 1) {
        if (tid < off) red[tid] += red[tid + off];
        __syncthreads();
    }
    if (tid == 0) out_loss[0] = 0.25f * red[0] * inv_n;
}

// ---------------------------------------------------------------------------
extern "C" void kernel_launch(void* const* d_in, const int* in_sizes, int n_in,
                              void* d_out, int out_size)
{
    const float* x = (const float*)d_in[0];
    const float* w = (const float*)d_in[1];
    float* out = (float*)d_out;

    const int n_x  = in_sizes[0];   // 8388608
    const int npos = n_x / C;       // 131072

    float* out_q    = out;
    float* out_idx  = out + n_x;
    float* out_loss = out + n_x + npos;

    const int smem_bytes = (E * RP + E) * (int)sizeof(float);  // ~141 KB
    cudaFuncSetAttribute(vq_fused_kernel,
                         cudaFuncAttributeMaxDynamicSharedMemorySize, smem_bytes);

    vq_fused_kernel<<<GRID, THREADS, smem_bytes>>>(x, w, out_q, out_idx, npos);
    loss_final_kernel<<<1, 256>>>(out_loss, GRID, 1.0f / (float)n_x);
}